// round 14
// baseline (speedup 1.0000x reference)
#include <cuda_runtime.h>
#include <cuda_fp16.h>
#include <cuda_bf16.h>
#include <cstdint>

#define S_LEN 4096
#define DIM   1280
#define NH    16
#define HD    80
#define SEG   512

// fp16 operands for the tensor GEMMs (single precision pass)
__device__ __half g_Ah[S_LEN * DIM];        // GEMM A (hs, then attn out)
__device__ __half g_Bh[3 * DIM * DIM];      // qkv weights fp16
__device__ __half g_Bp[DIM * DIM];          // proj weights fp16

// fp16 Q (pre-scaled by log2e/sqrt(hd), hi/lo), K (single), V (single) [H,S,D]
__device__ __half g_qh[NH * S_LEN * HD];
__device__ __half g_ql[NH * S_LEN * HD];
__device__ __half g_kh[NH * S_LEN * HD];
__device__ __half g_vh[NH * S_LEN * HD];

// ===========================================================================
// common PTX helpers
// ===========================================================================
#define LDSM4(r0, r1, r2, r3, addr) \
    asm volatile("ldmatrix.sync.aligned.m8n8.x4.shared.b16 {%0,%1,%2,%3}, [%4];" \
        : "=r"(r0), "=r"(r1), "=r"(r2), "=r"(r3) : "r"(addr))

#define LDSM4T(r0, r1, r2, r3, addr) \
    asm volatile("ldmatrix.sync.aligned.m8n8.x4.trans.shared.b16 {%0,%1,%2,%3}, [%4];" \
        : "=r"(r0), "=r"(r1), "=r"(r2), "=r"(r3) : "r"(addr))

#define MMA16816(d, a0, a1, a2, a3, b0, b1) \
    asm volatile("mma.sync.aligned.m16n8k16.row.col.f32.f16.f16.f32 " \
        "{%0,%1,%2,%3}, {%4,%5,%6,%7}, {%8,%9}, {%0,%1,%2,%3};" \
        : "+f"((d)[0]), "+f"((d)[1]), "+f"((d)[2]), "+f"((d)[3]) \
        : "r"(a0), "r"(a1), "r"(a2), "r"(a3), "r"(b0), "r"(b1))

#define CP_ASYNC16(dst, src) \
    asm volatile("cp.async.cg.shared.global [%0], [%1], 16;" :: "r"(dst), "l"(src))
#define CP_COMMIT() asm volatile("cp.async.commit_group;")
#define CP_WAIT1()  asm volatile("cp.async.wait_group 1;")
#define CP_WAIT0()  asm volatile("cp.async.wait_group 0;")

__device__ __forceinline__ uint32_t smem_u32(const void* p) {
    uint32_t a;
    asm("{ .reg .u64 t; cvta.to.shared.u64 t, %1; cvt.u32.u64 %0, t; }"
        : "=r"(a) : "l"(p));
    return a;
}

__device__ __forceinline__ uint32_t packh2(float x, float y) {
    __half2 h = __floats2half2_rn(x, y);
    return *(uint32_t*)&h;
}

__device__ __forceinline__ float ex2f(float x) {
    float r;
    asm("ex2.approx.f32 %0, %1;" : "=f"(r) : "f"(x));
    return r;
}

// ===========================================================================
// fused fp32 -> fp16 conversion of hs, qkv_w, proj_w (one launch)
// ===========================================================================
#define NA4 (S_LEN * DIM / 4)
#define NB4 (3 * DIM * DIM / 4)
#define NC4 (DIM * DIM / 4)

__global__ void conv_all(const float* __restrict__ a,
                         const float* __restrict__ b,
                         const float* __restrict__ c,
                         __half* __restrict__ oa,
                         __half* __restrict__ ob,
                         __half* __restrict__ oc)
{
    int i = blockIdx.x * blockDim.x + threadIdx.x;
    const float* src;
    __half* dst;
    int j;
    if (i < NA4)            { src = a; dst = oa; j = i; }
    else if (i < NA4 + NB4) { src = b; dst = ob; j = i - NA4; }
    else if (i < NA4 + NB4 + NC4) { src = c; dst = oc; j = i - NA4 - NB4; }
    else return;
    float4 v = ((const float4*)src)[j];
    __half2 hp0(__float2half(v.x), __float2half(v.y));
    __half2 hp1(__float2half(v.z), __float2half(v.w));
    uint2 hv;
    hv.x = *(uint32_t*)&hp0; hv.y = *(uint32_t*)&hp1;
    ((uint2*)dst)[j] = hv;
}

// ===========================================================================
// QKV GEMM with fused RoPE epilogue.
// CTA tile 128x160 (two heads wide), 4 warps (2M x 2N), warp tile 64x80.
// Epilogue: bias + rope on fp32 accumulators, writes g_qh/g_ql/g_kh/g_vh
// fp16 [H,S,D] directly. rotate-half partner d+40 = fragment nt+5 (same
// thread); cos(d+40)==cos(d) by construction.
// ===========================================================================
#define ROWB    80
#define TILE_A  (128 * ROWB)            // 10240 B
#define TILE_BQ (160 * ROWB)            // 12800 B
#define QSTAGE  (TILE_A + TILE_BQ)      // 23040 B
#define QSMEM_TOTAL (3 * QSTAGE)        // 69120 B

__global__ void __launch_bounds__(128, 2)
gemm_qkv_rope(const __half* __restrict__ Ah,
              const __half* __restrict__ Bh,
              const float* __restrict__ bias,
              const float* __restrict__ cosb,
              const float* __restrict__ sinb)
{
    extern __shared__ char gsm[];
    const uint32_t sb = smem_u32(gsm);
    const int K = DIM;

    const int tid = threadIdx.x;
    const int wid = tid >> 5;
    const int L   = tid & 31;
    const int bm  = blockIdx.y * 128;
    const int bn  = blockIdx.x * 160;
    const int wm  = (wid & 1) * 64;
    const int wn  = (wid >> 1) * 80;

    const int r0 = tid >> 2, q0 = (tid & 3);

    uint32_t a_off[4], b_off[5];
#pragma unroll
    for (int mt = 0; mt < 4; ++mt)
        a_off[mt] = (uint32_t)((wm + mt * 16 + (L & 7) + ((L >> 3) & 1) * 8) * ROWB
                               + (L >> 4) * 16);
#pragma unroll
    for (int np = 0; np < 5; ++np)
        b_off[np] = (uint32_t)((wn + np * 16 + (L & 7) + (L >> 4) * 8) * ROWB
                               + ((L >> 3) & 1) * 16);

    float acc[4][10][4];
#pragma unroll
    for (int mt = 0; mt < 4; ++mt)
#pragma unroll
        for (int nt = 0; nt < 10; ++nt)
#pragma unroll
            for (int i = 0; i < 4; ++i) acc[mt][nt][i] = 0.f;

    const int nstg = K / 32;   // 40

    auto issue = [&](int s) {
        const uint32_t dst = sb + (uint32_t)((s % 3) * QSTAGE);
        const int k0 = s * 32;
#pragma unroll
        for (int rr = 0; rr < 4; ++rr) {
            const int r = r0 + rr * 32;
            CP_ASYNC16(dst + r * ROWB + q0 * 16,
                       Ah + (size_t)(bm + r) * K + k0 + q0 * 8);
        }
#pragma unroll
        for (int rr = 0; rr < 5; ++rr) {
            const int r = r0 + rr * 32;
            CP_ASYNC16(dst + TILE_A + r * ROWB + q0 * 16,
                       Bh + (size_t)(bn + r) * K + k0 + q0 * 8);
        }
        CP_COMMIT();
    };

    issue(0);
    issue(1);

    for (int s = 0; s < nstg; ++s) {
        if (s + 1 < nstg) CP_WAIT1(); else CP_WAIT0();
        __syncthreads();
        if (s + 2 < nstg) issue(s + 2);

        const uint32_t base = sb + (uint32_t)((s % 3) * QSTAGE);

#pragma unroll
        for (int ks = 0; ks < 2; ++ks) {
            const uint32_t kcol = ks * 32;
            uint32_t ah[4][4], bh[5][4];
#pragma unroll
            for (int mt = 0; mt < 4; ++mt)
                LDSM4(ah[mt][0], ah[mt][1], ah[mt][2], ah[mt][3],
                      base + a_off[mt] + kcol);
#pragma unroll
            for (int np = 0; np < 5; ++np)
                LDSM4(bh[np][0], bh[np][1], bh[np][2], bh[np][3],
                      base + TILE_A + b_off[np] + kcol);
#pragma unroll
            for (int mt = 0; mt < 4; ++mt)
#pragma unroll
                for (int np = 0; np < 5; ++np)
#pragma unroll
                    for (int hf = 0; hf < 2; ++hf)
                        MMA16816(acc[mt][np * 2 + hf],
                                 ah[mt][0], ah[mt][1], ah[mt][2], ah[mt][3],
                                 bh[np][hf * 2], bh[np][hf * 2 + 1]);
        }
    }

    // ---- fused epilogue: bias + rope + fp16 stores into [H,S,D] ----
    const int third = bn / DIM;                 // 0=q, 1=k, 2=v
    const int h     = ((bn % DIM) + wn) / HD;   // head index 0..15
    const float qscale = 0.11180339887498948f * 1.4426950408889634f;

    // bias (invariant over rows): per np, cols d0.. and d0+40..
    float2 bia1[5], bia2[5];
#pragma unroll
    for (int np = 0; np < 5; ++np) {
        const int cb = bn + wn + np * 8 + (L & 3) * 2;
        bia1[np] = *(const float2*)(bias + cb);
        bia2[np] = *(const float2*)(bias + cb + 40);
    }

#pragma unroll
    for (int mt = 0; mt < 4; ++mt) {
        const int rbase = bm + wm + mt * 16 + (L >> 2);
#pragma unroll
        for (int np = 0; np < 5; ++np) {
            const int d0 = np * 8 + (L & 3) * 2;   // 0..38 even
#pragma unroll
            for (int rr = 0; rr < 2; ++rr) {
                const int r = rbase + rr * 8;
                float x1a = acc[mt][np][rr * 2 + 0] + bia1[np].x;      // d0
                float x1b = acc[mt][np][rr * 2 + 1] + bia1[np].y;      // d0+1
                float x2a = acc[mt][np + 5][rr * 2 + 0] + bia2[np].x;  // d0+40
                float x2b = acc[mt][np + 5][rr * 2 + 1] + bia2[np].y;
                const size_t o1 = ((size_t)h * S_LEN + r) * HD + d0;
                const size_t o2 = o1 + 40;
                if (third == 2) {
                    *(uint32_t*)(g_vh + o1) = packh2(x1a, x1b);
                    *(uint32_t*)(g_vh + o2) = packh2(x2a, x2b);
                } else {
                    float2 cs = *(const float2*)(cosb + r * HD + d0);
                    float2 sn = *(const float2*)(sinb + r * HD + d0);
                    float r1a = x1a * cs.x - x2a * sn.x;
                    float r1b = x1b * cs.y - x2b * sn.y;
                    float r2a = x2a * cs.x + x1a * sn.x;
                    float r2b = x2b * cs.y + x1b * sn.y;
                    if (third == 1) {
                        *(uint32_t*)(g_kh + o1) = packh2(r1a, r1b);
                        *(uint32_t*)(g_kh + o2) = packh2(r2a, r2b);
                    } else {
                        r1a *= qscale; r1b *= qscale;
                        r2a *= qscale; r2b *= qscale;
                        uint32_t h1 = packh2(r1a, r1b);
                        uint32_t h2 = packh2(r2a, r2b);
                        __half2 hh1 = *(__half2*)&h1, hh2 = *(__half2*)&h2;
                        *(uint32_t*)(g_qh + o1) = h1;
                        *(uint32_t*)(g_qh + o2) = h2;
                        *(uint32_t*)(g_ql + o1) =
                            packh2(r1a - __low2float(hh1), r1b - __high2float(hh1));
                        *(uint32_t*)(g_ql + o2) =
                            packh2(r2a - __low2float(hh2), r2b - __high2float(hh2));
                    }
                }
            }
        }
    }
}

// ===========================================================================
// fp16 GEMM: C = A @ B^T + bias  (proj; unchanged from R13)
// CTA 128x128, 4 warps, warp tile 64x64, BK=32, 3-stage cp.async.
// ===========================================================================
#define TILE_B (128 * ROWB)
#define STAGE_B (2 * TILE_B)           // A|B = 20480 B
#define GSMEM_TOTAL (3 * STAGE_B)      // 61440 B

__global__ void __launch_bounds__(128, 2)
gemm_fp16(const __half* __restrict__ Ah,
          const __half* __restrict__ Bh,
          const float* __restrict__ bias, float* __restrict__ C,
          int M, int N, int K)
{
    extern __shared__ char gsm[];
    const uint32_t sb = smem_u32(gsm);

    const int tid = threadIdx.x;
    const int wid = tid >> 5;
    const int L   = tid & 31;
    const int bm  = blockIdx.y * 128;
    const int bn  = blockIdx.x * 128;
    const int wm  = (wid & 1) * 64;
    const int wn  = (wid >> 1) * 64;

    const int r0 = tid >> 2, q0 = (tid & 3);

    uint32_t a_off[4], b_off[4];
#pragma unroll
    for (int mt = 0; mt < 4; ++mt)
        a_off[mt] = (uint32_t)((wm + mt * 16 + (L & 7) + ((L >> 3) & 1) * 8) * ROWB
                               + (L >> 4) * 16);
#pragma unroll
    for (int np = 0; np < 4; ++np)
        b_off[np] = (uint32_t)((wn + np * 16 + (L & 7) + (L >> 4) * 8) * ROWB
                               + ((L >> 3) & 1) * 16);

    float acc[4][8][4];
#pragma unroll
    for (int mt = 0; mt < 4; ++mt)
#pragma unroll
        for (int nt = 0; nt < 8; ++nt)
#pragma unroll
            for (int i = 0; i < 4; ++i) acc[mt][nt][i] = 0.f;

    const int nstg = K / 32;

    auto issue = [&](int s) {
        const uint32_t dst = sb + (uint32_t)((s % 3) * STAGE_B);
        const int k0 = s * 32;
#pragma unroll
        for (int rr = 0; rr < 4; ++rr) {
            const int r = r0 + rr * 32;
            const uint32_t d = dst + r * ROWB + q0 * 16;
            CP_ASYNC16(d + 0 * TILE_B, Ah + (size_t)(bm + r) * K + k0 + q0 * 8);
            CP_ASYNC16(d + 1 * TILE_B, Bh + (size_t)(bn + r) * K + k0 + q0 * 8);
        }
        CP_COMMIT();
    };

    issue(0);
    issue(1);

    for (int s = 0; s < nstg; ++s) {
        if (s + 1 < nstg) CP_WAIT1(); else CP_WAIT0();
        __syncthreads();
        if (s + 2 < nstg) issue(s + 2);

        const uint32_t base = sb + (uint32_t)((s % 3) * STAGE_B);

        uint32_t ah[2][4][4], bh[2][4][4];
#pragma unroll
        for (int ks = 0; ks < 2; ++ks) {
            const uint32_t kcol = ks * 32;
#pragma unroll
            for (int mt = 0; mt < 4; ++mt)
                LDSM4(ah[ks][mt][0], ah[ks][mt][1], ah[ks][mt][2], ah[ks][mt][3],
                      base + 0 * TILE_B + a_off[mt] + kcol);
#pragma unroll
            for (int np = 0; np < 4; ++np)
                LDSM4(bh[ks][np][0], bh[ks][np][1], bh[ks][np][2], bh[ks][np][3],
                      base + 1 * TILE_B + b_off[np] + kcol);
        }
#pragma unroll
        for (int ks = 0; ks < 2; ++ks)
#pragma unroll
            for (int mt = 0; mt < 4; ++mt)
#pragma unroll
                for (int np = 0; np < 4; ++np)
#pragma unroll
                    for (int hf = 0; hf < 2; ++hf)
                        MMA16816(acc[mt][np * 2 + hf],
                                 ah[ks][mt][0], ah[ks][mt][1],
                                 ah[ks][mt][2], ah[ks][mt][3],
                                 bh[ks][np][hf * 2], bh[ks][np][hf * 2 + 1]);
    }

#pragma unroll
    for (int mt = 0; mt < 4; ++mt) {
        const int row = bm + wm + mt * 16 + (L >> 2);
#pragma unroll
        for (int nt = 0; nt < 8; ++nt) {
            const int col = bn + wn + nt * 8 + (L & 3) * 2;
            float2 bv = *(const float2*)(bias + col);
            float2 o0, o1;
            o0.x = acc[mt][nt][0] + bv.x; o0.y = acc[mt][nt][1] + bv.y;
            o1.x = acc[mt][nt][2] + bv.x; o1.y = acc[mt][nt][3] + bv.y;
            *(float2*)(C + (size_t)row * N + col)       = o0;
            *(float2*)(C + (size_t)(row + 8) * N + col) = o1;
        }
    }
}

// ---------------------------------------------------------------------------
// Tensor-core flash attention (unchanged from R13).
// QK^T 2-pass ((Qh+Ql)·Kh); P·V single pass; fixed-max base-2 softmax.
// ---------------------------------------------------------------------------
#define AKS   88
#define ATILE (64 * AKS * 2)           // 11264 B per 64x80 tile
#define ATTN_SMEM (4 * ATILE)          // 2 bufs x (Kh|Vh) = 45056 B

__global__ void __launch_bounds__(128, 2) attn_tc()
{
    extern __shared__ char smb[];
    const uint32_t sb = smem_u32(smb);

    const int tid = threadIdx.x;
    const int wid = tid >> 5;
    const int L   = tid & 31;
    const int qt  = blockIdx.x & 7;
    const int sg  = (blockIdx.x >> 3) & 7;
    const int h   = blockIdx.x >> 6;
    const int s0  = sg * SEG + qt * 64;
    const int wm  = wid * 16;
    const int g4  = L >> 2;
    const int t4  = L & 3;

    // ---- stage Q hi/lo (tiles 0,1) and load A fragments ----
    {
        const __half* Qhg = g_qh + ((size_t)h * S_LEN + s0) * HD;
        const __half* Qlg = g_ql + ((size_t)h * S_LEN + s0) * HD;
#pragma unroll
        for (int i = 0; i < 5; ++i) {
            int idx = i * 128 + tid;
            int r = idx / 10, cc = idx % 10;
            CP_ASYNC16(sb + 0 * ATILE + r * 176 + cc * 16, Qhg + r * HD + cc * 8);
            CP_ASYNC16(sb + 1 * ATILE + r * 176 + cc * 16, Qlg + r * HD + cc * 8);
        }
        CP_COMMIT(); CP_WAIT0();
    }
    __syncthreads();

    uint32_t qfh[5][4], qfl[5][4];
    {
        const uint32_t abase =
            (uint32_t)((wm + (L & 7) + ((L >> 3) & 1) * 8) * 176 + (L >> 4) * 16);
#pragma unroll
        for (int ks = 0; ks < 5; ++ks) {
            LDSM4(qfh[ks][0], qfh[ks][1], qfh[ks][2], qfh[ks][3],
                  sb + 0 * ATILE + abase + ks * 32);
            LDSM4(qfl[ks][0], qfl[ks][1], qfl[ks][2], qfl[ks][3],
                  sb + 1 * ATILE + abase + ks * 32);
        }
    }
    __syncthreads();

    float o[10][4];
#pragma unroll
    for (int nt = 0; nt < 10; ++nt)
#pragma unroll
        for (int i = 0; i < 4; ++i) o[nt][i] = 0.f;
    float l0 = 0.f, l1 = 0.f;

    const uint32_t bbase =
        (uint32_t)(((L & 7) + ((L >> 3) & 1) * 8) * 176 + (L >> 4) * 16);

    auto issueKV = [&](int kc, int b) {
        const size_t gb = ((size_t)h * S_LEN + sg * SEG + kc * 64) * HD;
        const __half* src[2] = { g_kh + gb, g_vh + gb };
#pragma unroll
        for (int t = 0; t < 2; ++t) {
            const __half* p = src[t];
            const uint32_t db = sb + (uint32_t)((b * 2 + t) * ATILE);
#pragma unroll
            for (int i = 0; i < 5; ++i) {
                int idx = i * 128 + tid;
                int r = idx / 10, cc = idx % 10;
                CP_ASYNC16(db + r * 176 + cc * 16, p + r * HD + cc * 8);
            }
        }
        CP_COMMIT();
    };

    issueKV(0, 0);
    issueKV(1, 1);

    for (int kc = 0; kc < 8; ++kc) {
        if (kc < 7) CP_WAIT1(); else CP_WAIT0();
        __syncthreads();
        const uint32_t kb = sb + (uint32_t)(((kc & 1) * 2) * ATILE);

        float s[8][4];
#pragma unroll
        for (int nt = 0; nt < 8; ++nt)
#pragma unroll
            for (int i = 0; i < 4; ++i) s[nt][i] = 0.f;

#pragma unroll
        for (int ks = 0; ks < 5; ++ks) {
#pragma unroll
            for (int np = 0; np < 4; ++np) {
                uint32_t bh0, bh1, bh2, bh3;
                const uint32_t ka = bbase + np * (16 * 176) + ks * 32;
                LDSM4(bh0, bh1, bh2, bh3, kb + ka);
                MMA16816(s[2 * np], qfh[ks][0], qfh[ks][1], qfh[ks][2], qfh[ks][3], bh0, bh2);
                MMA16816(s[2 * np + 1], qfh[ks][0], qfh[ks][1], qfh[ks][2], qfh[ks][3], bh1, bh3);
                MMA16816(s[2 * np], qfl[ks][0], qfl[ks][1], qfl[ks][2], qfl[ks][3], bh0, bh2);
                MMA16816(s[2 * np + 1], qfl[ks][0], qfl[ks][1], qfl[ks][2], qfl[ks][3], bh1, bh3);
            }
        }

#pragma unroll
        for (int nt = 0; nt < 8; ++nt) {
            s[nt][0] = ex2f(s[nt][0]);
            s[nt][1] = ex2f(s[nt][1]);
            s[nt][2] = ex2f(s[nt][2]);
            s[nt][3] = ex2f(s[nt][3]);
            l0 += s[nt][0] + s[nt][1];
            l1 += s[nt][2] + s[nt][3];
        }

#pragma unroll
        for (int kt = 0; kt < 4; ++kt) {
            uint32_t ah0 = packh2(s[2 * kt][0], s[2 * kt][1]);
            uint32_t ah1 = packh2(s[2 * kt][2], s[2 * kt][3]);
            uint32_t ah2 = packh2(s[2 * kt + 1][0], s[2 * kt + 1][1]);
            uint32_t ah3 = packh2(s[2 * kt + 1][2], s[2 * kt + 1][3]);
#pragma unroll
            for (int vp = 0; vp < 5; ++vp) {
                const uint32_t va = bbase + kt * (16 * 176) + vp * 32;
                uint32_t v0, v1, v2, v3;
                LDSM4T(v0, v1, v2, v3, kb + 1 * ATILE + va);
                MMA16816(o[2 * vp], ah0, ah1, ah2, ah3, v0, v1);
                MMA16816(o[2 * vp + 1], ah0, ah1, ah2, ah3, v2, v3);
            }
        }
        __syncthreads();
        if (kc + 2 < 8) issueKV(kc + 2, kc & 1);
    }

    l0 += __shfl_xor_sync(0xffffffffu, l0, 1);
    l0 += __shfl_xor_sync(0xffffffffu, l0, 2);
    l1 += __shfl_xor_sync(0xffffffffu, l1, 1);
    l1 += __shfl_xor_sync(0xffffffffu, l1, 2);
    const float inv0 = 1.f / l0, inv1 = 1.f / l1;
    const int r0 = s0 + wm + g4;
    const int r1 = r0 + 8;
    const int colb = h * HD + t4 * 2;
#pragma unroll
    for (int nt = 0; nt < 10; ++nt) {
        const int col = colb + nt * 8;
        *(uint32_t*)(g_Ah + (size_t)r0 * DIM + col) =
            packh2(o[nt][0] * inv0, o[nt][1] * inv0);
        *(uint32_t*)(g_Ah + (size_t)r1 * DIM + col) =
            packh2(o[nt][2] * inv1, o[nt][3] * inv1);
    }
}

// ---------------------------------------------------------------------------
extern "C" void kernel_launch(void* const* d_in, const int* in_sizes, int n_in,
                              void* d_out, int out_size)
{
    const float* hs     = (const float*)d_in[0];
    const float* cosb   = (const float*)d_in[1];
    const float* sinb   = (const float*)d_in[2];
    const float* qkv_w  = (const float*)d_in[3];
    const float* qkv_b  = (const float*)d_in[4];
    const float* proj_w = (const float*)d_in[5];
    const float* proj_b = (const float*)d_in[6];
    float* out = (float*)d_out;

    __half *ah, *bh, *bp;
    cudaGetSymbolAddress((void**)&ah, g_Ah);
    cudaGetSymbolAddress((void**)&bh, g_Bh);
    cudaGetSymbolAddress((void**)&bp, g_Bp);

    cudaFuncSetAttribute(gemm_qkv_rope,
                         cudaFuncAttributeMaxDynamicSharedMemorySize, QSMEM_TOTAL);
    cudaFuncSetAttribute(gemm_fp16,
                         cudaFuncAttributeMaxDynamicSharedMemorySize, GSMEM_TOTAL);
    cudaFuncSetAttribute(attn_tc,
                         cudaFuncAttributeMaxDynamicSharedMemorySize, ATTN_SMEM);

    // 1) prep: convert hs, qkv_w, proj_w to fp16 (single launch)
    {
        int total = NA4 + NB4 + NC4;
        conv_all<<<(total + 255) / 256, 256>>>(hs, qkv_w, proj_w, ah, bh, bp);
    }
    // 2) QKV GEMM + fused RoPE -> g_qh/g_ql/g_kh/g_vh
    {
        dim3 grid(3 * DIM / 160, S_LEN / 128);   // 24 x 32
        gemm_qkv_rope<<<grid, 128, QSMEM_TOTAL>>>(ah, bh, qkv_b, cosb, sinb);
    }
    // 3) Tensor-core attention -> writes proj A operand directly
    attn_tc<<<NH * 8 * 8, 128, ATTN_SMEM>>>();
    // 4) Proj GEMM
    {
        dim3 grid(DIM / 128, S_LEN / 128);
        gemm_fp16<<<grid, 128, GSMEM_TOTAL>>>(ah, bp, proj_b, out,
                                              S_LEN, DIM, DIM);
    }
}

// round 15
// speedup vs baseline: 1.0934x; 1.0934x over previous
#include <cuda_runtime.h>
#include <cuda_fp16.h>
#include <cuda_bf16.h>
#include <cstdint>

#define S_LEN 4096
#define DIM   1280
#define NH    16
#define HD    80
#define SEG   512

// fp16 operands for the tensor GEMMs (single precision pass)
__device__ __half g_Ah[S_LEN * DIM];        // GEMM A (hs, then attn out)
__device__ __half g_Bh[3 * DIM * DIM];      // qkv weights fp16
__device__ __half g_Bp[DIM * DIM];          // proj weights fp16

// fp16 Q (pre-scaled by log2e/sqrt(hd), hi/lo), K (single), V (single) [H,S,D]
__device__ __half g_qh[NH * S_LEN * HD];
__device__ __half g_ql[NH * S_LEN * HD];
__device__ __half g_kh[NH * S_LEN * HD];
__device__ __half g_vh[NH * S_LEN * HD];

// ===========================================================================
// common PTX helpers
// ===========================================================================
#define LDSM4(r0, r1, r2, r3, addr) \
    asm volatile("ldmatrix.sync.aligned.m8n8.x4.shared.b16 {%0,%1,%2,%3}, [%4];" \
        : "=r"(r0), "=r"(r1), "=r"(r2), "=r"(r3) : "r"(addr))

#define LDSM4T(r0, r1, r2, r3, addr) \
    asm volatile("ldmatrix.sync.aligned.m8n8.x4.trans.shared.b16 {%0,%1,%2,%3}, [%4];" \
        : "=r"(r0), "=r"(r1), "=r"(r2), "=r"(r3) : "r"(addr))

#define MMA16816(d, a0, a1, a2, a3, b0, b1) \
    asm volatile("mma.sync.aligned.m16n8k16.row.col.f32.f16.f16.f32 " \
        "{%0,%1,%2,%3}, {%4,%5,%6,%7}, {%8,%9}, {%0,%1,%2,%3};" \
        : "+f"((d)[0]), "+f"((d)[1]), "+f"((d)[2]), "+f"((d)[3]) \
        : "r"(a0), "r"(a1), "r"(a2), "r"(a3), "r"(b0), "r"(b1))

#define CP_ASYNC16(dst, src) \
    asm volatile("cp.async.cg.shared.global [%0], [%1], 16;" :: "r"(dst), "l"(src))
#define CP_COMMIT() asm volatile("cp.async.commit_group;")
#define CP_WAIT1()  asm volatile("cp.async.wait_group 1;")
#define CP_WAIT0()  asm volatile("cp.async.wait_group 0;")

__device__ __forceinline__ uint32_t smem_u32(const void* p) {
    uint32_t a;
    asm("{ .reg .u64 t; cvta.to.shared.u64 t, %1; cvt.u32.u64 %0, t; }"
        : "=r"(a) : "l"(p));
    return a;
}

__device__ __forceinline__ uint32_t packh2(float x, float y) {
    __half2 h = __floats2half2_rn(x, y);
    return *(uint32_t*)&h;
}

__device__ __forceinline__ float ex2f(float x) {
    float r;
    asm("ex2.approx.f32 %0, %1;" : "=f"(r) : "f"(x));
    return r;
}

// ===========================================================================
// fused fp32 -> fp16 conversion of hs, qkv_w, proj_w (one launch)
// ===========================================================================
#define NA4 (S_LEN * DIM / 4)
#define NB4 (3 * DIM * DIM / 4)
#define NC4 (DIM * DIM / 4)

__global__ void conv_all(const float* __restrict__ a,
                         const float* __restrict__ b,
                         const float* __restrict__ c,
                         __half* __restrict__ oa,
                         __half* __restrict__ ob,
                         __half* __restrict__ oc)
{
    int i = blockIdx.x * blockDim.x + threadIdx.x;
    const float* src;
    __half* dst;
    int j;
    if (i < NA4)            { src = a; dst = oa; j = i; }
    else if (i < NA4 + NB4) { src = b; dst = ob; j = i - NA4; }
    else if (i < NA4 + NB4 + NC4) { src = c; dst = oc; j = i - NA4 - NB4; }
    else return;
    float4 v = ((const float4*)src)[j];
    __half2 hp0(__float2half(v.x), __float2half(v.y));
    __half2 hp1(__float2half(v.z), __float2half(v.w));
    uint2 hv;
    hv.x = *(uint32_t*)&hp0; hv.y = *(uint32_t*)&hp1;
    ((uint2*)dst)[j] = hv;
}

// ===========================================================================
// QKV GEMM with fused RoPE epilogue — 8 warps (256 thr), warp tile 32x80.
// CTA tile 128x160 (two heads wide). Epilogue: bias + rope on fp32
// accumulators, fp16 stores into g_qh/g_ql/g_kh/g_vh [H,S,D].
// rotate-half partner d+40 = fragment np+5 (same thread); cos(d+40)==cos(d).
// ===========================================================================
#define ROWB    80
#define TILE_A  (128 * ROWB)            // 10240 B
#define TILE_BQ (160 * ROWB)            // 12800 B
#define QSTAGE  (TILE_A + TILE_BQ)      // 23040 B
#define QSMEM_TOTAL (3 * QSTAGE)        // 69120 B

__global__ void __launch_bounds__(256, 2)
gemm_qkv_rope(const __half* __restrict__ Ah,
              const __half* __restrict__ Bh,
              const float* __restrict__ bias,
              const float* __restrict__ cosb,
              const float* __restrict__ sinb)
{
    extern __shared__ char gsm[];
    const uint32_t sb = smem_u32(gsm);
    const int K = DIM;

    const int tid = threadIdx.x;
    const int wid = tid >> 5;
    const int L   = tid & 31;
    const int bm  = blockIdx.y * 128;
    const int bn  = blockIdx.x * 160;
    const int wm  = (wid & 3) * 32;     // 4 M-warps of 32 rows
    const int wn  = (wid >> 2) * 80;    // 2 N-warps of 80 cols (1 head)

    const int r0 = tid >> 2, q0 = (tid & 3);   // r0: 0..63

    uint32_t a_off[2], b_off[5];
#pragma unroll
    for (int mt = 0; mt < 2; ++mt)
        a_off[mt] = (uint32_t)((wm + mt * 16 + (L & 7) + ((L >> 3) & 1) * 8) * ROWB
                               + (L >> 4) * 16);
#pragma unroll
    for (int np = 0; np < 5; ++np)
        b_off[np] = (uint32_t)((wn + np * 16 + (L & 7) + (L >> 4) * 8) * ROWB
                               + ((L >> 3) & 1) * 16);

    float acc[2][10][4];
#pragma unroll
    for (int mt = 0; mt < 2; ++mt)
#pragma unroll
        for (int nt = 0; nt < 10; ++nt)
#pragma unroll
            for (int i = 0; i < 4; ++i) acc[mt][nt][i] = 0.f;

    const int nstg = K / 32;   // 40

    auto issue = [&](int s) {
        const uint32_t dst = sb + (uint32_t)((s % 3) * QSTAGE);
        const int k0 = s * 32;
#pragma unroll
        for (int rr = 0; rr < 2; ++rr) {
            const int r = r0 + rr * 64;
            CP_ASYNC16(dst + r * ROWB + q0 * 16,
                       Ah + (size_t)(bm + r) * K + k0 + q0 * 8);
            CP_ASYNC16(dst + TILE_A + r * ROWB + q0 * 16,
                       Bh + (size_t)(bn + r) * K + k0 + q0 * 8);
        }
        if (r0 < 32) {
            const int r = 128 + r0;
            CP_ASYNC16(dst + TILE_A + r * ROWB + q0 * 16,
                       Bh + (size_t)(bn + r) * K + k0 + q0 * 8);
        }
        CP_COMMIT();
    };

    issue(0);
    issue(1);

    for (int s = 0; s < nstg; ++s) {
        if (s + 1 < nstg) CP_WAIT1(); else CP_WAIT0();
        __syncthreads();
        if (s + 2 < nstg) issue(s + 2);

        const uint32_t base = sb + (uint32_t)((s % 3) * QSTAGE);

#pragma unroll
        for (int ks = 0; ks < 2; ++ks) {
            const uint32_t kcol = ks * 32;
            uint32_t ah[2][4], bh[5][4];
#pragma unroll
            for (int mt = 0; mt < 2; ++mt)
                LDSM4(ah[mt][0], ah[mt][1], ah[mt][2], ah[mt][3],
                      base + a_off[mt] + kcol);
#pragma unroll
            for (int np = 0; np < 5; ++np)
                LDSM4(bh[np][0], bh[np][1], bh[np][2], bh[np][3],
                      base + TILE_A + b_off[np] + kcol);
#pragma unroll
            for (int mt = 0; mt < 2; ++mt)
#pragma unroll
                for (int np = 0; np < 5; ++np)
#pragma unroll
                    for (int hf = 0; hf < 2; ++hf)
                        MMA16816(acc[mt][np * 2 + hf],
                                 ah[mt][0], ah[mt][1], ah[mt][2], ah[mt][3],
                                 bh[np][hf * 2], bh[np][hf * 2 + 1]);
        }
    }

    // ---- fused epilogue: bias + rope + fp16 stores into [H,S,D] ----
    const int third = bn / DIM;                 // 0=q, 1=k, 2=v
    const int h     = ((bn % DIM) + wn) / HD;   // head index 0..15
    const float qscale = 0.11180339887498948f * 1.4426950408889634f;

    float2 bia1[5], bia2[5];
#pragma unroll
    for (int np = 0; np < 5; ++np) {
        const int cb = bn + wn + np * 8 + (L & 3) * 2;
        bia1[np] = *(const float2*)(bias + cb);
        bia2[np] = *(const float2*)(bias + cb + 40);
    }

#pragma unroll
    for (int mt = 0; mt < 2; ++mt) {
        const int rbase = bm + wm + mt * 16 + (L >> 2);
#pragma unroll
        for (int np = 0; np < 5; ++np) {
            const int d0 = np * 8 + (L & 3) * 2;   // 0..38 even
#pragma unroll
            for (int rr = 0; rr < 2; ++rr) {
                const int r = rbase + rr * 8;
                float x1a = acc[mt][np][rr * 2 + 0] + bia1[np].x;      // d0
                float x1b = acc[mt][np][rr * 2 + 1] + bia1[np].y;      // d0+1
                float x2a = acc[mt][np + 5][rr * 2 + 0] + bia2[np].x;  // d0+40
                float x2b = acc[mt][np + 5][rr * 2 + 1] + bia2[np].y;
                const size_t o1 = ((size_t)h * S_LEN + r) * HD + d0;
                const size_t o2 = o1 + 40;
                if (third == 2) {
                    *(uint32_t*)(g_vh + o1) = packh2(x1a, x1b);
                    *(uint32_t*)(g_vh + o2) = packh2(x2a, x2b);
                } else {
                    float2 cs = *(const float2*)(cosb + r * HD + d0);
                    float2 sn = *(const float2*)(sinb + r * HD + d0);
                    float r1a = x1a * cs.x - x2a * sn.x;
                    float r1b = x1b * cs.y - x2b * sn.y;
                    float r2a = x2a * cs.x + x1a * sn.x;
                    float r2b = x2b * cs.y + x1b * sn.y;
                    if (third == 1) {
                        *(uint32_t*)(g_kh + o1) = packh2(r1a, r1b);
                        *(uint32_t*)(g_kh + o2) = packh2(r2a, r2b);
                    } else {
                        r1a *= qscale; r1b *= qscale;
                        r2a *= qscale; r2b *= qscale;
                        uint32_t h1 = packh2(r1a, r1b);
                        uint32_t h2 = packh2(r2a, r2b);
                        __half2 hh1 = *(__half2*)&h1, hh2 = *(__half2*)&h2;
                        *(uint32_t*)(g_qh + o1) = h1;
                        *(uint32_t*)(g_qh + o2) = h2;
                        *(uint32_t*)(g_ql + o1) =
                            packh2(r1a - __low2float(hh1), r1b - __high2float(hh1));
                        *(uint32_t*)(g_ql + o2) =
                            packh2(r2a - __low2float(hh2), r2b - __high2float(hh2));
                    }
                }
            }
        }
    }
}

// ===========================================================================
// proj GEMM: C = A @ B^T + bias.  CTA 64x128, 4 warps, warp tile 32x64,
// BK=32, 3-stage cp.async, 3 CTAs/SM (640 CTAs -> good wave balance).
// ===========================================================================
#define PTILE_A (64 * ROWB)             // 5120 B
#define PTILE_B (128 * ROWB)            // 10240 B
#define PSTAGE  (PTILE_A + PTILE_B)     // 15360 B
#define PSMEM_TOTAL (3 * PSTAGE)        // 46080 B

__global__ void __launch_bounds__(128, 3)
gemm_proj(const __half* __restrict__ Ah,
          const __half* __restrict__ Bh,
          const float* __restrict__ bias, float* __restrict__ C)
{
    extern __shared__ char gsm[];
    const uint32_t sb = smem_u32(gsm);
    const int K = DIM, N = DIM;

    const int tid = threadIdx.x;
    const int wid = tid >> 5;
    const int L   = tid & 31;
    const int bm  = blockIdx.y * 64;
    const int bn  = blockIdx.x * 128;
    const int wm  = (wid & 1) * 32;
    const int wn  = (wid >> 1) * 64;

    const int r0 = tid >> 2, q0 = (tid & 3);   // r0: 0..31

    uint32_t a_off[2], b_off[4];
#pragma unroll
    for (int mt = 0; mt < 2; ++mt)
        a_off[mt] = (uint32_t)((wm + mt * 16 + (L & 7) + ((L >> 3) & 1) * 8) * ROWB
                               + (L >> 4) * 16);
#pragma unroll
    for (int np = 0; np < 4; ++np)
        b_off[np] = (uint32_t)((wn + np * 16 + (L & 7) + (L >> 4) * 8) * ROWB
                               + ((L >> 3) & 1) * 16);

    float acc[2][8][4];
#pragma unroll
    for (int mt = 0; mt < 2; ++mt)
#pragma unroll
        for (int nt = 0; nt < 8; ++nt)
#pragma unroll
            for (int i = 0; i < 4; ++i) acc[mt][nt][i] = 0.f;

    const int nstg = K / 32;

    auto issue = [&](int s) {
        const uint32_t dst = sb + (uint32_t)((s % 3) * PSTAGE);
        const int k0 = s * 32;
#pragma unroll
        for (int rr = 0; rr < 2; ++rr) {
            const int r = r0 + rr * 32;
            CP_ASYNC16(dst + r * ROWB + q0 * 16,
                       Ah + (size_t)(bm + r) * K + k0 + q0 * 8);
        }
#pragma unroll
        for (int rr = 0; rr < 4; ++rr) {
            const int r = r0 + rr * 32;
            CP_ASYNC16(dst + PTILE_A + r * ROWB + q0 * 16,
                       Bh + (size_t)(bn + r) * K + k0 + q0 * 8);
        }
        CP_COMMIT();
    };

    issue(0);
    issue(1);

    for (int s = 0; s < nstg; ++s) {
        if (s + 1 < nstg) CP_WAIT1(); else CP_WAIT0();
        __syncthreads();
        if (s + 2 < nstg) issue(s + 2);

        const uint32_t base = sb + (uint32_t)((s % 3) * PSTAGE);

#pragma unroll
        for (int ks = 0; ks < 2; ++ks) {
            const uint32_t kcol = ks * 32;
            uint32_t ah[2][4], bh[4][4];
#pragma unroll
            for (int mt = 0; mt < 2; ++mt)
                LDSM4(ah[mt][0], ah[mt][1], ah[mt][2], ah[mt][3],
                      base + a_off[mt] + kcol);
#pragma unroll
            for (int np = 0; np < 4; ++np)
                LDSM4(bh[np][0], bh[np][1], bh[np][2], bh[np][3],
                      base + PTILE_A + b_off[np] + kcol);
#pragma unroll
            for (int mt = 0; mt < 2; ++mt)
#pragma unroll
                for (int np = 0; np < 4; ++np)
#pragma unroll
                    for (int hf = 0; hf < 2; ++hf)
                        MMA16816(acc[mt][np * 2 + hf],
                                 ah[mt][0], ah[mt][1], ah[mt][2], ah[mt][3],
                                 bh[np][hf * 2], bh[np][hf * 2 + 1]);
        }
    }

#pragma unroll
    for (int mt = 0; mt < 2; ++mt) {
        const int row = bm + wm + mt * 16 + (L >> 2);
#pragma unroll
        for (int nt = 0; nt < 8; ++nt) {
            const int col = bn + wn + nt * 8 + (L & 3) * 2;
            float2 bv = *(const float2*)(bias + col);
            float2 o0, o1;
            o0.x = acc[mt][nt][0] + bv.x; o0.y = acc[mt][nt][1] + bv.y;
            o1.x = acc[mt][nt][2] + bv.x; o1.y = acc[mt][nt][3] + bv.y;
            *(float2*)(C + (size_t)row * N + col)       = o0;
            *(float2*)(C + (size_t)(row + 8) * N + col) = o1;
        }
    }
}

// ---------------------------------------------------------------------------
// Tensor-core flash attention (unchanged from R13).
// QK^T 2-pass ((Qh+Ql)·Kh); P·V single pass; fixed-max base-2 softmax.
// ---------------------------------------------------------------------------
#define AKS   88
#define ATILE (64 * AKS * 2)           // 11264 B per 64x80 tile
#define ATTN_SMEM (4 * ATILE)          // 2 bufs x (Kh|Vh) = 45056 B

__global__ void __launch_bounds__(128, 2) attn_tc()
{
    extern __shared__ char smb[];
    const uint32_t sb = smem_u32(smb);

    const int tid = threadIdx.x;
    const int wid = tid >> 5;
    const int L   = tid & 31;
    const int qt  = blockIdx.x & 7;
    const int sg  = (blockIdx.x >> 3) & 7;
    const int h   = blockIdx.x >> 6;
    const int s0  = sg * SEG + qt * 64;
    const int wm  = wid * 16;
    const int g4  = L >> 2;
    const int t4  = L & 3;

    {
        const __half* Qhg = g_qh + ((size_t)h * S_LEN + s0) * HD;
        const __half* Qlg = g_ql + ((size_t)h * S_LEN + s0) * HD;
#pragma unroll
        for (int i = 0; i < 5; ++i) {
            int idx = i * 128 + tid;
            int r = idx / 10, cc = idx % 10;
            CP_ASYNC16(sb + 0 * ATILE + r * 176 + cc * 16, Qhg + r * HD + cc * 8);
            CP_ASYNC16(sb + 1 * ATILE + r * 176 + cc * 16, Qlg + r * HD + cc * 8);
        }
        CP_COMMIT(); CP_WAIT0();
    }
    __syncthreads();

    uint32_t qfh[5][4], qfl[5][4];
    {
        const uint32_t abase =
            (uint32_t)((wm + (L & 7) + ((L >> 3) & 1) * 8) * 176 + (L >> 4) * 16);
#pragma unroll
        for (int ks = 0; ks < 5; ++ks) {
            LDSM4(qfh[ks][0], qfh[ks][1], qfh[ks][2], qfh[ks][3],
                  sb + 0 * ATILE + abase + ks * 32);
            LDSM4(qfl[ks][0], qfl[ks][1], qfl[ks][2], qfl[ks][3],
                  sb + 1 * ATILE + abase + ks * 32);
        }
    }
    __syncthreads();

    float o[10][4];
#pragma unroll
    for (int nt = 0; nt < 10; ++nt)
#pragma unroll
        for (int i = 0; i < 4; ++i) o[nt][i] = 0.f;
    float l0 = 0.f, l1 = 0.f;

    const uint32_t bbase =
        (uint32_t)(((L & 7) + ((L >> 3) & 1) * 8) * 176 + (L >> 4) * 16);

    auto issueKV = [&](int kc, int b) {
        const size_t gb = ((size_t)h * S_LEN + sg * SEG + kc * 64) * HD;
        const __half* src[2] = { g_kh + gb, g_vh + gb };
#pragma unroll
        for (int t = 0; t < 2; ++t) {
            const __half* p = src[t];
            const uint32_t db = sb + (uint32_t)((b * 2 + t) * ATILE);
#pragma unroll
            for (int i = 0; i < 5; ++i) {
                int idx = i * 128 + tid;
                int r = idx / 10, cc = idx % 10;
                CP_ASYNC16(db + r * 176 + cc * 16, p + r * HD + cc * 8);
            }
        }
        CP_COMMIT();
    };

    issueKV(0, 0);
    issueKV(1, 1);

    for (int kc = 0; kc < 8; ++kc) {
        if (kc < 7) CP_WAIT1(); else CP_WAIT0();
        __syncthreads();
        const uint32_t kb = sb + (uint32_t)(((kc & 1) * 2) * ATILE);

        float s[8][4];
#pragma unroll
        for (int nt = 0; nt < 8; ++nt)
#pragma unroll
            for (int i = 0; i < 4; ++i) s[nt][i] = 0.f;

#pragma unroll
        for (int ks = 0; ks < 5; ++ks) {
#pragma unroll
            for (int np = 0; np < 4; ++np) {
                uint32_t bh0, bh1, bh2, bh3;
                const uint32_t ka = bbase + np * (16 * 176) + ks * 32;
                LDSM4(bh0, bh1, bh2, bh3, kb + ka);
                MMA16816(s[2 * np], qfh[ks][0], qfh[ks][1], qfh[ks][2], qfh[ks][3], bh0, bh2);
                MMA16816(s[2 * np + 1], qfh[ks][0], qfh[ks][1], qfh[ks][2], qfh[ks][3], bh1, bh3);
                MMA16816(s[2 * np], qfl[ks][0], qfl[ks][1], qfl[ks][2], qfl[ks][3], bh0, bh2);
                MMA16816(s[2 * np + 1], qfl[ks][0], qfl[ks][1], qfl[ks][2], qfl[ks][3], bh1, bh3);
            }
        }

#pragma unroll
        for (int nt = 0; nt < 8; ++nt) {
            s[nt][0] = ex2f(s[nt][0]);
            s[nt][1] = ex2f(s[nt][1]);
            s[nt][2] = ex2f(s[nt][2]);
            s[nt][3] = ex2f(s[nt][3]);
            l0 += s[nt][0] + s[nt][1];
            l1 += s[nt][2] + s[nt][3];
        }

#pragma unroll
        for (int kt = 0; kt < 4; ++kt) {
            uint32_t ah0 = packh2(s[2 * kt][0], s[2 * kt][1]);
            uint32_t ah1 = packh2(s[2 * kt][2], s[2 * kt][3]);
            uint32_t ah2 = packh2(s[2 * kt + 1][0], s[2 * kt + 1][1]);
            uint32_t ah3 = packh2(s[2 * kt + 1][2], s[2 * kt + 1][3]);
#pragma unroll
            for (int vp = 0; vp < 5; ++vp) {
                const uint32_t va = bbase + kt * (16 * 176) + vp * 32;
                uint32_t v0, v1, v2, v3;
                LDSM4T(v0, v1, v2, v3, kb + 1 * ATILE + va);
                MMA16816(o[2 * vp], ah0, ah1, ah2, ah3, v0, v1);
                MMA16816(o[2 * vp + 1], ah0, ah1, ah2, ah3, v2, v3);
            }
        }
        __syncthreads();
        if (kc + 2 < 8) issueKV(kc + 2, kc & 1);
    }

    l0 += __shfl_xor_sync(0xffffffffu, l0, 1);
    l0 += __shfl_xor_sync(0xffffffffu, l0, 2);
    l1 += __shfl_xor_sync(0xffffffffu, l1, 1);
    l1 += __shfl_xor_sync(0xffffffffu, l1, 2);
    const float inv0 = 1.f / l0, inv1 = 1.f / l1;
    const int r0 = s0 + wm + g4;
    const int r1 = r0 + 8;
    const int colb = h * HD + t4 * 2;
#pragma unroll
    for (int nt = 0; nt < 10; ++nt) {
        const int col = colb + nt * 8;
        *(uint32_t*)(g_Ah + (size_t)r0 * DIM + col) =
            packh2(o[nt][0] * inv0, o[nt][1] * inv0);
        *(uint32_t*)(g_Ah + (size_t)r1 * DIM + col) =
            packh2(o[nt][2] * inv1, o[nt][3] * inv1);
    }
}

// ---------------------------------------------------------------------------
extern "C" void kernel_launch(void* const* d_in, const int* in_sizes, int n_in,
                              void* d_out, int out_size)
{
    const float* hs     = (const float*)d_in[0];
    const float* cosb   = (const float*)d_in[1];
    const float* sinb   = (const float*)d_in[2];
    const float* qkv_w  = (const float*)d_in[3];
    const float* qkv_b  = (const float*)d_in[4];
    const float* proj_w = (const float*)d_in[5];
    const float* proj_b = (const float*)d_in[6];
    float* out = (float*)d_out;

    __half *ah, *bh, *bp;
    cudaGetSymbolAddress((void**)&ah, g_Ah);
    cudaGetSymbolAddress((void**)&bh, g_Bh);
    cudaGetSymbolAddress((void**)&bp, g_Bp);

    cudaFuncSetAttribute(gemm_qkv_rope,
                         cudaFuncAttributeMaxDynamicSharedMemorySize, QSMEM_TOTAL);
    cudaFuncSetAttribute(gemm_proj,
                         cudaFuncAttributeMaxDynamicSharedMemorySize, PSMEM_TOTAL);
    cudaFuncSetAttribute(attn_tc,
                         cudaFuncAttributeMaxDynamicSharedMemorySize, ATTN_SMEM);

    // 1) prep: convert hs, qkv_w, proj_w to fp16 (single launch)
    {
        int total = NA4 + NB4 + NC4;
        conv_all<<<(total + 255) / 256, 256>>>(hs, qkv_w, proj_w, ah, bh, bp);
    }
    // 2) QKV GEMM + fused RoPE -> g_qh/g_ql/g_kh/g_vh
    {
        dim3 grid(3 * DIM / 160, S_LEN / 128);   // 24 x 32
        gemm_qkv_rope<<<grid, 256, QSMEM_TOTAL>>>(ah, bh, qkv_b, cosb, sinb);
    }
    // 3) Tensor-core attention -> writes proj A operand directly
    attn_tc<<<NH * 8 * 8, 128, ATTN_SMEM>>>();
    // 4) Proj GEMM (64x128 tiles, 640 CTAs)
    {
        dim3 grid(DIM / 128, S_LEN / 64);        // 10 x 64
        gemm_proj<<<grid, 128, PSMEM_TOTAL>>>(ah, bp, proj_b, out);
    }
}

// round 16
// speedup vs baseline: 1.1218x; 1.0259x over previous
#include <cuda_runtime.h>
#include <cuda_fp16.h>
#include <cuda_bf16.h>
#include <cstdint>

#define S_LEN 4096
#define DIM   1280
#define NH    16
#define HD    80
#define SEG   512

// fp16 operands for the tensor GEMMs (single precision pass)
__device__ __half g_Ah[S_LEN * DIM];        // GEMM A (hs, then attn out)
__device__ __half g_Bh[3 * DIM * DIM];      // qkv weights fp16
__device__ __half g_Bp[DIM * DIM];          // proj weights fp16

// fp16 Q (pre-scaled by log2e/sqrt(hd), hi/lo), K (single), V (single) [H,S,D]
__device__ __half g_qh[NH * S_LEN * HD];
__device__ __half g_ql[NH * S_LEN * HD];
__device__ __half g_kh[NH * S_LEN * HD];
__device__ __half g_vh[NH * S_LEN * HD];

// ===========================================================================
// common PTX helpers
// ===========================================================================
#define LDSM4(r0, r1, r2, r3, addr) \
    asm volatile("ldmatrix.sync.aligned.m8n8.x4.shared.b16 {%0,%1,%2,%3}, [%4];" \
        : "=r"(r0), "=r"(r1), "=r"(r2), "=r"(r3) : "r"(addr))

#define LDSM4T(r0, r1, r2, r3, addr) \
    asm volatile("ldmatrix.sync.aligned.m8n8.x4.trans.shared.b16 {%0,%1,%2,%3}, [%4];" \
        : "=r"(r0), "=r"(r1), "=r"(r2), "=r"(r3) : "r"(addr))

#define MMA16816(d, a0, a1, a2, a3, b0, b1) \
    asm volatile("mma.sync.aligned.m16n8k16.row.col.f32.f16.f16.f32 " \
        "{%0,%1,%2,%3}, {%4,%5,%6,%7}, {%8,%9}, {%0,%1,%2,%3};" \
        : "+f"((d)[0]), "+f"((d)[1]), "+f"((d)[2]), "+f"((d)[3]) \
        : "r"(a0), "r"(a1), "r"(a2), "r"(a3), "r"(b0), "r"(b1))

#define CP_ASYNC16(dst, src) \
    asm volatile("cp.async.cg.shared.global [%0], [%1], 16;" :: "r"(dst), "l"(src))
#define CP_COMMIT() asm volatile("cp.async.commit_group;")
#define CP_WAIT1()  asm volatile("cp.async.wait_group 1;")
#define CP_WAIT0()  asm volatile("cp.async.wait_group 0;")

__device__ __forceinline__ uint32_t smem_u32(const void* p) {
    uint32_t a;
    asm("{ .reg .u64 t; cvta.to.shared.u64 t, %1; cvt.u32.u64 %0, t; }"
        : "=r"(a) : "l"(p));
    return a;
}

__device__ __forceinline__ uint32_t packh2(float x, float y) {
    __half2 h = __floats2half2_rn(x, y);
    return *(uint32_t*)&h;
}

__device__ __forceinline__ float ex2f(float x) {
    float r;
    asm("ex2.approx.f32 %0, %1;" : "=f"(r) : "f"(x));
    return r;
}

// ===========================================================================
// fused fp32 -> fp16 conversion of hs, qkv_w, proj_w (one launch)
// ===========================================================================
#define NA4 (S_LEN * DIM / 4)
#define NB4 (3 * DIM * DIM / 4)
#define NC4 (DIM * DIM / 4)

__global__ void conv_all(const float* __restrict__ a,
                         const float* __restrict__ b,
                         const float* __restrict__ c,
                         __half* __restrict__ oa,
                         __half* __restrict__ ob,
                         __half* __restrict__ oc)
{
    int i = blockIdx.x * blockDim.x + threadIdx.x;
    const float* src;
    __half* dst;
    int j;
    if (i < NA4)            { src = a; dst = oa; j = i; }
    else if (i < NA4 + NB4) { src = b; dst = ob; j = i - NA4; }
    else if (i < NA4 + NB4 + NC4) { src = c; dst = oc; j = i - NA4 - NB4; }
    else return;
    float4 v = ((const float4*)src)[j];
    __half2 hp0(__float2half(v.x), __float2half(v.y));
    __half2 hp1(__float2half(v.z), __float2half(v.w));
    uint2 hv;
    hv.x = *(uint32_t*)&hp0; hv.y = *(uint32_t*)&hp1;
    ((uint2*)dst)[j] = hv;
}

// ===========================================================================
// QKV GEMM with fused RoPE epilogue — 8 warps (256 thr), warp tile 32x80.
// CTA tile 128x160 (two heads wide). Epilogue: bias + rope on fp32
// accumulators, fp16 stores into g_qh/g_ql/g_kh/g_vh [H,S,D].
// rotate-half partner d+40 = fragment np+5 (same thread); cos(d+40)==cos(d).
// ===========================================================================
#define ROWB    80
#define TILE_A  (128 * ROWB)            // 10240 B
#define TILE_BQ (160 * ROWB)            // 12800 B
#define QSTAGE  (TILE_A + TILE_BQ)      // 23040 B
#define QSMEM_TOTAL (3 * QSTAGE)        // 69120 B

__global__ void __launch_bounds__(256, 2)
gemm_qkv_rope(const __half* __restrict__ Ah,
              const __half* __restrict__ Bh,
              const float* __restrict__ bias,
              const float* __restrict__ cosb,
              const float* __restrict__ sinb)
{
    extern __shared__ char gsm[];
    const uint32_t sb = smem_u32(gsm);
    const int K = DIM;

    const int tid = threadIdx.x;
    const int wid = tid >> 5;
    const int L   = tid & 31;
    const int bm  = blockIdx.y * 128;
    const int bn  = blockIdx.x * 160;
    const int wm  = (wid & 3) * 32;     // 4 M-warps of 32 rows
    const int wn  = (wid >> 2) * 80;    // 2 N-warps of 80 cols (1 head)

    const int r0 = tid >> 2, q0 = (tid & 3);   // r0: 0..63

    uint32_t a_off[2], b_off[5];
#pragma unroll
    for (int mt = 0; mt < 2; ++mt)
        a_off[mt] = (uint32_t)((wm + mt * 16 + (L & 7) + ((L >> 3) & 1) * 8) * ROWB
                               + (L >> 4) * 16);
#pragma unroll
    for (int np = 0; np < 5; ++np)
        b_off[np] = (uint32_t)((wn + np * 16 + (L & 7) + (L >> 4) * 8) * ROWB
                               + ((L >> 3) & 1) * 16);

    float acc[2][10][4];
#pragma unroll
    for (int mt = 0; mt < 2; ++mt)
#pragma unroll
        for (int nt = 0; nt < 10; ++nt)
#pragma unroll
            for (int i = 0; i < 4; ++i) acc[mt][nt][i] = 0.f;

    const int nstg = K / 32;   // 40

    auto issue = [&](int s) {
        const uint32_t dst = sb + (uint32_t)((s % 3) * QSTAGE);
        const int k0 = s * 32;
#pragma unroll
        for (int rr = 0; rr < 2; ++rr) {
            const int r = r0 + rr * 64;
            CP_ASYNC16(dst + r * ROWB + q0 * 16,
                       Ah + (size_t)(bm + r) * K + k0 + q0 * 8);
            CP_ASYNC16(dst + TILE_A + r * ROWB + q0 * 16,
                       Bh + (size_t)(bn + r) * K + k0 + q0 * 8);
        }
        if (r0 < 32) {
            const int r = 128 + r0;
            CP_ASYNC16(dst + TILE_A + r * ROWB + q0 * 16,
                       Bh + (size_t)(bn + r) * K + k0 + q0 * 8);
        }
        CP_COMMIT();
    };

    issue(0);
    issue(1);

    for (int s = 0; s < nstg; ++s) {
        if (s + 1 < nstg) CP_WAIT1(); else CP_WAIT0();
        __syncthreads();
        if (s + 2 < nstg) issue(s + 2);

        const uint32_t base = sb + (uint32_t)((s % 3) * QSTAGE);

#pragma unroll
        for (int ks = 0; ks < 2; ++ks) {
            const uint32_t kcol = ks * 32;
            uint32_t ah[2][4], bh[5][4];
#pragma unroll
            for (int mt = 0; mt < 2; ++mt)
                LDSM4(ah[mt][0], ah[mt][1], ah[mt][2], ah[mt][3],
                      base + a_off[mt] + kcol);
#pragma unroll
            for (int np = 0; np < 5; ++np)
                LDSM4(bh[np][0], bh[np][1], bh[np][2], bh[np][3],
                      base + TILE_A + b_off[np] + kcol);
#pragma unroll
            for (int mt = 0; mt < 2; ++mt)
#pragma unroll
                for (int np = 0; np < 5; ++np)
#pragma unroll
                    for (int hf = 0; hf < 2; ++hf)
                        MMA16816(acc[mt][np * 2 + hf],
                                 ah[mt][0], ah[mt][1], ah[mt][2], ah[mt][3],
                                 bh[np][hf * 2], bh[np][hf * 2 + 1]);
        }
    }

    // ---- fused epilogue: bias + rope + fp16 stores into [H,S,D] ----
    const int third = bn / DIM;                 // 0=q, 1=k, 2=v
    const int h     = ((bn % DIM) + wn) / HD;   // head index 0..15
    const float qscale = 0.11180339887498948f * 1.4426950408889634f;

    float2 bia1[5], bia2[5];
#pragma unroll
    for (int np = 0; np < 5; ++np) {
        const int cb = bn + wn + np * 8 + (L & 3) * 2;
        bia1[np] = *(const float2*)(bias + cb);
        bia2[np] = *(const float2*)(bias + cb + 40);
    }

#pragma unroll
    for (int mt = 0; mt < 2; ++mt) {
        const int rbase = bm + wm + mt * 16 + (L >> 2);
#pragma unroll
        for (int np = 0; np < 5; ++np) {
            const int d0 = np * 8 + (L & 3) * 2;   // 0..38 even
#pragma unroll
            for (int rr = 0; rr < 2; ++rr) {
                const int r = rbase + rr * 8;
                float x1a = acc[mt][np][rr * 2 + 0] + bia1[np].x;      // d0
                float x1b = acc[mt][np][rr * 2 + 1] + bia1[np].y;      // d0+1
                float x2a = acc[mt][np + 5][rr * 2 + 0] + bia2[np].x;  // d0+40
                float x2b = acc[mt][np + 5][rr * 2 + 1] + bia2[np].y;
                const size_t o1 = ((size_t)h * S_LEN + r) * HD + d0;
                const size_t o2 = o1 + 40;
                if (third == 2) {
                    *(uint32_t*)(g_vh + o1) = packh2(x1a, x1b);
                    *(uint32_t*)(g_vh + o2) = packh2(x2a, x2b);
                } else {
                    float2 cs = *(const float2*)(cosb + r * HD + d0);
                    float2 sn = *(const float2*)(sinb + r * HD + d0);
                    float r1a = x1a * cs.x - x2a * sn.x;
                    float r1b = x1b * cs.y - x2b * sn.y;
                    float r2a = x2a * cs.x + x1a * sn.x;
                    float r2b = x2b * cs.y + x1b * sn.y;
                    if (third == 1) {
                        *(uint32_t*)(g_kh + o1) = packh2(r1a, r1b);
                        *(uint32_t*)(g_kh + o2) = packh2(r2a, r2b);
                    } else {
                        r1a *= qscale; r1b *= qscale;
                        r2a *= qscale; r2b *= qscale;
                        uint32_t h1 = packh2(r1a, r1b);
                        uint32_t h2 = packh2(r2a, r2b);
                        __half2 hh1 = *(__half2*)&h1, hh2 = *(__half2*)&h2;
                        *(uint32_t*)(g_qh + o1) = h1;
                        *(uint32_t*)(g_qh + o2) = h2;
                        *(uint32_t*)(g_ql + o1) =
                            packh2(r1a - __low2float(hh1), r1b - __high2float(hh1));
                        *(uint32_t*)(g_ql + o2) =
                            packh2(r2a - __low2float(hh2), r2b - __high2float(hh2));
                    }
                }
            }
        }
    }
}

// ===========================================================================
// proj GEMM: out = A @ Bp^T + bias, fp32 out.
// CTA tile 128x160, 8 warps, warp tile 32x80 — grid 8x32 = 256 CTAs:
// fits in ONE wave (296 slots at 2 CTA/SM), killing wave quantization.
// ===========================================================================
__global__ void __launch_bounds__(256, 2)
gemm_proj(const __half* __restrict__ Ah,
          const __half* __restrict__ Bh,
          const float* __restrict__ bias, float* __restrict__ C)
{
    extern __shared__ char gsm[];
    const uint32_t sb = smem_u32(gsm);
    const int K = DIM, N = DIM;

    const int tid = threadIdx.x;
    const int wid = tid >> 5;
    const int L   = tid & 31;
    const int bm  = blockIdx.y * 128;
    const int bn  = blockIdx.x * 160;
    const int wm  = (wid & 3) * 32;
    const int wn  = (wid >> 2) * 80;

    const int r0 = tid >> 2, q0 = (tid & 3);

    uint32_t a_off[2], b_off[5];
#pragma unroll
    for (int mt = 0; mt < 2; ++mt)
        a_off[mt] = (uint32_t)((wm + mt * 16 + (L & 7) + ((L >> 3) & 1) * 8) * ROWB
                               + (L >> 4) * 16);
#pragma unroll
    for (int np = 0; np < 5; ++np)
        b_off[np] = (uint32_t)((wn + np * 16 + (L & 7) + (L >> 4) * 8) * ROWB
                               + ((L >> 3) & 1) * 16);

    float acc[2][10][4];
#pragma unroll
    for (int mt = 0; mt < 2; ++mt)
#pragma unroll
        for (int nt = 0; nt < 10; ++nt)
#pragma unroll
            for (int i = 0; i < 4; ++i) acc[mt][nt][i] = 0.f;

    const int nstg = K / 32;

    auto issue = [&](int s) {
        const uint32_t dst = sb + (uint32_t)((s % 3) * QSTAGE);
        const int k0 = s * 32;
#pragma unroll
        for (int rr = 0; rr < 2; ++rr) {
            const int r = r0 + rr * 64;
            CP_ASYNC16(dst + r * ROWB + q0 * 16,
                       Ah + (size_t)(bm + r) * K + k0 + q0 * 8);
            CP_ASYNC16(dst + TILE_A + r * ROWB + q0 * 16,
                       Bh + (size_t)(bn + r) * K + k0 + q0 * 8);
        }
        if (r0 < 32) {
            const int r = 128 + r0;
            CP_ASYNC16(dst + TILE_A + r * ROWB + q0 * 16,
                       Bh + (size_t)(bn + r) * K + k0 + q0 * 8);
        }
        CP_COMMIT();
    };

    issue(0);
    issue(1);

    for (int s = 0; s < nstg; ++s) {
        if (s + 1 < nstg) CP_WAIT1(); else CP_WAIT0();
        __syncthreads();
        if (s + 2 < nstg) issue(s + 2);

        const uint32_t base = sb + (uint32_t)((s % 3) * QSTAGE);

#pragma unroll
        for (int ks = 0; ks < 2; ++ks) {
            const uint32_t kcol = ks * 32;
            uint32_t ah[2][4], bh[5][4];
#pragma unroll
            for (int mt = 0; mt < 2; ++mt)
                LDSM4(ah[mt][0], ah[mt][1], ah[mt][2], ah[mt][3],
                      base + a_off[mt] + kcol);
#pragma unroll
            for (int np = 0; np < 5; ++np)
                LDSM4(bh[np][0], bh[np][1], bh[np][2], bh[np][3],
                      base + TILE_A + b_off[np] + kcol);
#pragma unroll
            for (int mt = 0; mt < 2; ++mt)
#pragma unroll
                for (int np = 0; np < 5; ++np)
#pragma unroll
                    for (int hf = 0; hf < 2; ++hf)
                        MMA16816(acc[mt][np * 2 + hf],
                                 ah[mt][0], ah[mt][1], ah[mt][2], ah[mt][3],
                                 bh[np][hf * 2], bh[np][hf * 2 + 1]);
        }
    }

#pragma unroll
    for (int mt = 0; mt < 2; ++mt) {
        const int row = bm + wm + mt * 16 + (L >> 2);
#pragma unroll
        for (int nt = 0; nt < 10; ++nt) {
            const int col = bn + wn + nt * 8 + (L & 3) * 2;
            float2 bv = *(const float2*)(bias + col);
            float2 o0, o1;
            o0.x = acc[mt][nt][0] + bv.x; o0.y = acc[mt][nt][1] + bv.y;
            o1.x = acc[mt][nt][2] + bv.x; o1.y = acc[mt][nt][3] + bv.y;
            *(float2*)(C + (size_t)row * N + col)       = o0;
            *(float2*)(C + (size_t)(row + 8) * N + col) = o1;
        }
    }
}

// ---------------------------------------------------------------------------
// Tensor-core flash attention (unchanged from R13).
// QK^T 2-pass ((Qh+Ql)·Kh); P·V single pass; fixed-max base-2 softmax.
// ---------------------------------------------------------------------------
#define AKS   88
#define ATILE (64 * AKS * 2)           // 11264 B per 64x80 tile
#define ATTN_SMEM (4 * ATILE)          // 2 bufs x (Kh|Vh) = 45056 B

__global__ void __launch_bounds__(128, 2) attn_tc()
{
    extern __shared__ char smb[];
    const uint32_t sb = smem_u32(smb);

    const int tid = threadIdx.x;
    const int wid = tid >> 5;
    const int L   = tid & 31;
    const int qt  = blockIdx.x & 7;
    const int sg  = (blockIdx.x >> 3) & 7;
    const int h   = blockIdx.x >> 6;
    const int s0  = sg * SEG + qt * 64;
    const int wm  = wid * 16;
    const int g4  = L >> 2;
    const int t4  = L & 3;

    {
        const __half* Qhg = g_qh + ((size_t)h * S_LEN + s0) * HD;
        const __half* Qlg = g_ql + ((size_t)h * S_LEN + s0) * HD;
#pragma unroll
        for (int i = 0; i < 5; ++i) {
            int idx = i * 128 + tid;
            int r = idx / 10, cc = idx % 10;
            CP_ASYNC16(sb + 0 * ATILE + r * 176 + cc * 16, Qhg + r * HD + cc * 8);
            CP_ASYNC16(sb + 1 * ATILE + r * 176 + cc * 16, Qlg + r * HD + cc * 8);
        }
        CP_COMMIT(); CP_WAIT0();
    }
    __syncthreads();

    uint32_t qfh[5][4], qfl[5][4];
    {
        const uint32_t abase =
            (uint32_t)((wm + (L & 7) + ((L >> 3) & 1) * 8) * 176 + (L >> 4) * 16);
#pragma unroll
        for (int ks = 0; ks < 5; ++ks) {
            LDSM4(qfh[ks][0], qfh[ks][1], qfh[ks][2], qfh[ks][3],
                  sb + 0 * ATILE + abase + ks * 32);
            LDSM4(qfl[ks][0], qfl[ks][1], qfl[ks][2], qfl[ks][3],
                  sb + 1 * ATILE + abase + ks * 32);
        }
    }
    __syncthreads();

    float o[10][4];
#pragma unroll
    for (int nt = 0; nt < 10; ++nt)
#pragma unroll
        for (int i = 0; i < 4; ++i) o[nt][i] = 0.f;
    float l0 = 0.f, l1 = 0.f;

    const uint32_t bbase =
        (uint32_t)(((L & 7) + ((L >> 3) & 1) * 8) * 176 + (L >> 4) * 16);

    auto issueKV = [&](int kc, int b) {
        const size_t gb = ((size_t)h * S_LEN + sg * SEG + kc * 64) * HD;
        const __half* src[2] = { g_kh + gb, g_vh + gb };
#pragma unroll
        for (int t = 0; t < 2; ++t) {
            const __half* p = src[t];
            const uint32_t db = sb + (uint32_t)((b * 2 + t) * ATILE);
#pragma unroll
            for (int i = 0; i < 5; ++i) {
                int idx = i * 128 + tid;
                int r = idx / 10, cc = idx % 10;
                CP_ASYNC16(db + r * 176 + cc * 16, p + r * HD + cc * 8);
            }
        }
        CP_COMMIT();
    };

    issueKV(0, 0);
    issueKV(1, 1);

    for (int kc = 0; kc < 8; ++kc) {
        if (kc < 7) CP_WAIT1(); else CP_WAIT0();
        __syncthreads();
        const uint32_t kb = sb + (uint32_t)(((kc & 1) * 2) * ATILE);

        float s[8][4];
#pragma unroll
        for (int nt = 0; nt < 8; ++nt)
#pragma unroll
            for (int i = 0; i < 4; ++i) s[nt][i] = 0.f;

#pragma unroll
        for (int ks = 0; ks < 5; ++ks) {
#pragma unroll
            for (int np = 0; np < 4; ++np) {
                uint32_t bh0, bh1, bh2, bh3;
                const uint32_t ka = bbase + np * (16 * 176) + ks * 32;
                LDSM4(bh0, bh1, bh2, bh3, kb + ka);
                MMA16816(s[2 * np], qfh[ks][0], qfh[ks][1], qfh[ks][2], qfh[ks][3], bh0, bh2);
                MMA16816(s[2 * np + 1], qfh[ks][0], qfh[ks][1], qfh[ks][2], qfh[ks][3], bh1, bh3);
                MMA16816(s[2 * np], qfl[ks][0], qfl[ks][1], qfl[ks][2], qfl[ks][3], bh0, bh2);
                MMA16816(s[2 * np + 1], qfl[ks][0], qfl[ks][1], qfl[ks][2], qfl[ks][3], bh1, bh3);
            }
        }

#pragma unroll
        for (int nt = 0; nt < 8; ++nt) {
            s[nt][0] = ex2f(s[nt][0]);
            s[nt][1] = ex2f(s[nt][1]);
            s[nt][2] = ex2f(s[nt][2]);
            s[nt][3] = ex2f(s[nt][3]);
            l0 += s[nt][0] + s[nt][1];
            l1 += s[nt][2] + s[nt][3];
        }

#pragma unroll
        for (int kt = 0; kt < 4; ++kt) {
            uint32_t ah0 = packh2(s[2 * kt][0], s[2 * kt][1]);
            uint32_t ah1 = packh2(s[2 * kt][2], s[2 * kt][3]);
            uint32_t ah2 = packh2(s[2 * kt + 1][0], s[2 * kt + 1][1]);
            uint32_t ah3 = packh2(s[2 * kt + 1][2], s[2 * kt + 1][3]);
#pragma unroll
            for (int vp = 0; vp < 5; ++vp) {
                const uint32_t va = bbase + kt * (16 * 176) + vp * 32;
                uint32_t v0, v1, v2, v3;
                LDSM4T(v0, v1, v2, v3, kb + 1 * ATILE + va);
                MMA16816(o[2 * vp], ah0, ah1, ah2, ah3, v0, v1);
                MMA16816(o[2 * vp + 1], ah0, ah1, ah2, ah3, v2, v3);
            }
        }
        __syncthreads();
        if (kc + 2 < 8) issueKV(kc + 2, kc & 1);
    }

    l0 += __shfl_xor_sync(0xffffffffu, l0, 1);
    l0 += __shfl_xor_sync(0xffffffffu, l0, 2);
    l1 += __shfl_xor_sync(0xffffffffu, l1, 1);
    l1 += __shfl_xor_sync(0xffffffffu, l1, 2);
    const float inv0 = 1.f / l0, inv1 = 1.f / l1;
    const int r0 = s0 + wm + g4;
    const int r1 = r0 + 8;
    const int colb = h * HD + t4 * 2;
#pragma unroll
    for (int nt = 0; nt < 10; ++nt) {
        const int col = colb + nt * 8;
        *(uint32_t*)(g_Ah + (size_t)r0 * DIM + col) =
            packh2(o[nt][0] * inv0, o[nt][1] * inv0);
        *(uint32_t*)(g_Ah + (size_t)r1 * DIM + col) =
            packh2(o[nt][2] * inv1, o[nt][3] * inv1);
    }
}

// ---------------------------------------------------------------------------
extern "C" void kernel_launch(void* const* d_in, const int* in_sizes, int n_in,
                              void* d_out, int out_size)
{
    const float* hs     = (const float*)d_in[0];
    const float* cosb   = (const float*)d_in[1];
    const float* sinb   = (const float*)d_in[2];
    const float* qkv_w  = (const float*)d_in[3];
    const float* qkv_b  = (const float*)d_in[4];
    const float* proj_w = (const float*)d_in[5];
    const float* proj_b = (const float*)d_in[6];
    float* out = (float*)d_out;

    __half *ah, *bh, *bp;
    cudaGetSymbolAddress((void**)&ah, g_Ah);
    cudaGetSymbolAddress((void**)&bh, g_Bh);
    cudaGetSymbolAddress((void**)&bp, g_Bp);

    cudaFuncSetAttribute(gemm_qkv_rope,
                         cudaFuncAttributeMaxDynamicSharedMemorySize, QSMEM_TOTAL);
    cudaFuncSetAttribute(gemm_proj,
                         cudaFuncAttributeMaxDynamicSharedMemorySize, QSMEM_TOTAL);
    cudaFuncSetAttribute(attn_tc,
                         cudaFuncAttributeMaxDynamicSharedMemorySize, ATTN_SMEM);

    // 1) prep: convert hs, qkv_w, proj_w to fp16 (single launch)
    {
        int total = NA4 + NB4 + NC4;
        conv_all<<<(total + 255) / 256, 256>>>(hs, qkv_w, proj_w, ah, bh, bp);
    }
    // 2) QKV GEMM + fused RoPE -> g_qh/g_ql/g_kh/g_vh
    {
        dim3 grid(3 * DIM / 160, S_LEN / 128);   // 24 x 32
        gemm_qkv_rope<<<grid, 256, QSMEM_TOTAL>>>(ah, bh, qkv_b, cosb, sinb);
    }
    // 3) Tensor-core attention -> writes proj A operand directly
    attn_tc<<<NH * 8 * 8, 128, ATTN_SMEM>>>();
    // 4) Proj GEMM (128x160 tiles -> 256 CTAs = single wave)
    {
        dim3 grid(DIM / 160, S_LEN / 128);       // 8 x 32
        gemm_proj<<<grid, 256, QSMEM_TOTAL>>>(ah, bp, proj_b, out);
    }
}